// round 1
// baseline (speedup 1.0000x reference)
#include <cuda_runtime.h>
#include <math.h>

#define BN   64
#define PAST 128
#define FUT  64
#define NF   51
#define NO   50
#define NH   4
#define N1   (BN*PAST)   /* 8192 */
#define N2   (BN*FUT)    /* 4096 */
#define E1N  (N1*16)     /* 131072 */
#define E2N  (N2*16)     /* 65536 */
#define T1   (E1N+N1)    /* 139264 */
#define T2   (E2N+N2)    /* 69632 */

// ---------------- scratch (static device globals; no allocation) ----------------
__device__ float d_x  [N1*NF];
__device__ float d_x2 [N2*NF];
__device__ float d_h1 [N1*NH*NO];      // 8192 x 200
__device__ float d_as1[N1*NH];
__device__ float d_ad1[N1*NH];
__device__ float d_x1o[N1*NO];
__device__ float d_M  [NO*NO];
__device__ float d_q1h[N1];
__device__ float d_z2 [N2*NO];
__device__ float d_tmp[N2];
__device__ float d_h2 [N2*NH];
__device__ float d_as2[N2*NH];
__device__ float d_ad2[N2*NH];
__device__ int   d_cnt1[N1];
__device__ int   d_off1[N1+1];
__device__ int   d_cur1[N1];
__device__ int   d_csr1[T1];
__device__ int   d_cnt2[N2];
__device__ int   d_off2[N2+1];
__device__ int   d_cur2[N2];
__device__ int   d_csr2[T2];

// ---------------- helpers ----------------
__device__ __forceinline__ float warp_max(float v) {
    #pragma unroll
    for (int o = 16; o; o >>= 1) v = fmaxf(v, __shfl_xor_sync(0xffffffffu, v, o));
    return v;
}
__device__ __forceinline__ float warp_sum(float v) {
    #pragma unroll
    for (int o = 16; o; o >>= 1) v += __shfl_xor_sync(0xffffffffu, v, o);
    return v;
}
__device__ __forceinline__ float lrelu(float x) { return x > 0.f ? x : 0.2f * x; }

// ---------------- 1. preprocess: embedding concat ----------------
__global__ void k_pre(const int* cat1, const float* num1,
                      const int* cat2, const float* num2,
                      const float* e0, const float* e1, const float* e2) {
    int n = blockIdx.x;
    int t = threadIdx.x;
    if (t >= NF) return;
    const int*   cat;
    const float* num;
    float*       xo;
    int ln;
    if (n < N1) { cat = cat1; num = num1; xo = d_x;  ln = n; }
    else        { cat = cat2; num = num2; xo = d_x2; ln = n - N1; }
    float v;
    if      (t < 16) v = e0[cat[ln*3+0]*16 + t];
    else if (t < 24) v = e1[cat[ln*3+1]*8  + (t-16)];
    else if (t < 48) v = e2[cat[ln*3+2]*24 + (t-24)];
    else             v = num[ln*3 + (t-48)];
    xo[ln*NF + t] = v;
}

// ---------------- 2. M = 2 * W @ W^T (50x50), W is (50,64) ----------------
__global__ void k_M(const float* W) {
    int i = blockIdx.x, j = threadIdx.x;
    if (j >= NO) return;
    float s = 0.f;
    #pragma unroll
    for (int k = 0; k < 64; k++) s += W[i*64+k] * W[j*64+k];
    d_M[i*NO+j] = 2.f * s;
}

// ---------------- 3. GAT1 linear: h1 = x @ g1_lin  + attention scalars ----------------
__global__ void k_gemm1(const float* lin, const float* asrc, const float* adst) {
    int n = blockIdx.x, t = threadIdx.x;
    __shared__ float xs[NF];
    __shared__ float hs[NH*NO];
    if (t < NF) xs[t] = d_x[n*NF + t];
    __syncthreads();
    if (t < NH*NO) {
        float acc = 0.f;
        #pragma unroll
        for (int k = 0; k < NF; k++) acc += xs[k] * lin[k*(NH*NO) + t];
        hs[t] = acc;
        d_h1[n*(NH*NO) + t] = acc;
    }
    __syncthreads();
    if (t < 8) {
        int head = t & 3;
        const float* att = (t < 4) ? asrc : adst;
        float a = 0.f;
        #pragma unroll
        for (int c = 0; c < NO; c++) a += hs[head*NO + c] * att[head*NO + c];
        if (t < 4) d_as1[n*NH + head] = a;
        else       d_ad1[n*NH + head] = a;
    }
}

// ---------------- CSR build (g=0: graph1, g=1: graph2) ----------------
__global__ void k_initcnt(int g) {
    int i = blockIdx.x*blockDim.x + threadIdx.x;
    int n = g ? N2 : N1;
    if (i < n) (g ? d_cnt2 : d_cnt1)[i] = 1;  // self loop pre-counted
}
__global__ void k_hist(const int* edges, int g) {
    int i = blockIdx.x*blockDim.x + threadIdx.x;
    int E = g ? E2N : E1N;
    if (i < E) atomicAdd(&(g ? d_cnt2 : d_cnt1)[edges[E + i]], 1);
}
__global__ void k_scan(int g) {  // single block, 1024 threads
    const int n = g ? N2 : N1;
    int* cnt = g ? d_cnt2 : d_cnt1;
    int* off = g ? d_off2 : d_off1;
    int* cur = g ? d_cur2 : d_cur1;
    __shared__ int part[1024];
    int t = threadIdx.x;
    int chunk = n / 1024;
    int start = t * chunk;
    int s = 0;
    for (int i = 0; i < chunk; i++) s += cnt[start + i];
    part[t] = s;
    __syncthreads();
    for (int d = 1; d < 1024; d <<= 1) {
        int v = (t >= d) ? part[t-d] : 0;
        __syncthreads();
        part[t] += v;
        __syncthreads();
    }
    int run = (t == 0) ? 0 : part[t-1];
    for (int i = 0; i < chunk; i++) {
        off[start+i] = run; cur[start+i] = run; run += cnt[start+i];
    }
    if (t == 1023) off[n] = run;
}
__global__ void k_scatter(const int* edges, int g) {
    int i = blockIdx.x*blockDim.x + threadIdx.x;
    int E = g ? E2N : E1N;
    int n = g ? N2 : N1;
    if (i >= E + n) return;
    int s, d;
    if (i < E) { s = edges[i]; d = edges[E + i]; }
    else       { s = d = i - E; }
    int pos = atomicAdd(&(g ? d_cur2 : d_cur1)[d], 1);
    (g ? d_csr2 : d_csr1)[pos] = s;
}

// ---------------- 4. GAT1 aggregation: block per dst, warp per head ----------------
__global__ void k_gat1_agg(const float* bias) {
    int n = blockIdx.x;
    int w = threadIdx.x >> 5;   // head
    int lane = threadIdx.x & 31;
    int beg = d_off1[n], end = d_off1[n+1];
    float adst = d_ad1[n*NH + w];

    // pass 1: max over edges (lanes strided)
    float m = -1e30f;
    for (int i = beg + lane; i < end; i += 32) {
        int s = d_csr1[i];
        m = fmaxf(m, lrelu(d_as1[s*NH + w] + adst));
    }
    m = warp_max(m);

    // pass 2: lanes over channels, edges serial
    float acc0 = 0.f, acc1 = 0.f, ssum = 0.f;
    int c0 = lane, c1 = lane + 32;
    for (int i = beg; i < end; i++) {
        int s = d_csr1[i];
        float e  = lrelu(d_as1[s*NH + w] + adst);
        float ex = expf(e - m);
        ssum += ex;
        const float* hr = &d_h1[s*(NH*NO) + w*NO];
        acc0 += ex * hr[c0];
        if (c1 < NO) acc1 += ex * hr[c1];
    }
    float inv = 0.25f / (ssum + 1e-16f);

    __shared__ float so[NO];
    if (threadIdx.x < NO) so[threadIdx.x] = 0.f;
    __syncthreads();
    atomicAdd(&so[c0], acc0 * inv);
    if (c1 < NO) atomicAdd(&so[c1], acc1 * inv);
    __syncthreads();
    if (threadIdx.x < NO)
        d_x1o[n*NO + threadIdx.x] = so[threadIdx.x] + bias[threadIdx.x];
}

// ---------------- 5. q1half[n] = -0.5 * x1 M x1 ----------------
__global__ void k_quad() {
    int n = blockIdx.x, t = threadIdx.x;
    __shared__ float xs[NO];
    __shared__ float red[64];
    if (t < NO) xs[t] = d_x1o[n*NO + t];
    __syncthreads();
    float p = 0.f;
    if (t < NO) {
        float mi = 0.f;
        #pragma unroll
        for (int j = 0; j < NO; j++) mi += d_M[t*NO + j] * xs[j];
        p = mi * xs[t];
    }
    red[t] = p;
    __syncthreads();
    for (int s = 32; s; s >>= 1) { if (t < s) red[t] += red[t+s]; __syncthreads(); }
    if (t == 0) d_q1h[n] = -0.5f * red[0];
}

// ---------------- 6. z2 = M @ x2[:, :50] ----------------
__global__ void k_z2() {
    int n = blockIdx.x, t = threadIdx.x;
    __shared__ float xs[NO];
    if (t < NO) xs[t] = d_x2[n*NF + t];
    __syncthreads();
    if (t < NO) {
        float z = 0.f;
        #pragma unroll
        for (int j = 0; j < NO; j++) z += d_M[t*NO + j] * xs[j];
        d_z2[n*NO + t] = z;
    }
}

// ---------------- 7. attention softmax + tmp = alpha @ y_past ----------------
__global__ void k_attn(const int* A) {
    int n = blockIdx.x;            // n = b*64 + f
    int b = n >> 6, f = n & 63;
    int t = threadIdx.x;           // t = p in [0,128)
    __shared__ float zs[NO];
    __shared__ float red[128];
    if (t < NO) zs[t] = d_z2[n*NO + t];
    __syncthreads();
    int node = b*PAST + t;
    float dot = 0.f;
    #pragma unroll
    for (int c = 0; c < NO; c++) dot += zs[c] * d_x1o[node*NO + c];
    float logit = d_q1h[node] + dot;
    int mk = A[t*(PAST+FUT) + PAST + f];
    if (mk == 0) logit = -INFINITY;

    red[t] = logit;
    __syncthreads();
    for (int s = 64; s; s >>= 1) { if (t < s) red[t] = fmaxf(red[t], red[t+s]); __syncthreads(); }
    float m = red[0];
    __syncthreads();
    float ex = (logit == -INFINITY) ? 0.f : expf(logit - m);
    red[t] = ex;
    __syncthreads();
    for (int s = 64; s; s >>= 1) { if (t < s) red[t] += red[t+s]; __syncthreads(); }
    float ssum = red[0];
    __syncthreads();
    float y = d_x[node*NF + (NF-1)];
    red[t] = ex * y;
    __syncthreads();
    for (int s = 64; s; s >>= 1) { if (t < s) red[t] += red[t+s]; __syncthreads(); }
    if (t == 0) d_tmp[n] = red[0] / ssum;
}

// ---------------- 8. GAT2 linear + attention scalars ----------------
__global__ void k_gat2_pre(const float* lin, const float* asrc, const float* adst) {
    int n = blockIdx.x*blockDim.x + threadIdx.x;
    if (n >= N2) return;
    float acc[NH] = {0.f, 0.f, 0.f, 0.f};
    #pragma unroll 10
    for (int k = 0; k < NO; k++) {
        float xv = d_x2[n*NF + k];
        #pragma unroll
        for (int h = 0; h < NH; h++) acc[h] += xv * lin[k*NH + h];
    }
    float tv = d_tmp[n];
    #pragma unroll
    for (int h = 0; h < NH; h++) {
        float v = acc[h] + tv * lin[NO*NH + h];
        d_h2[n*NH + h]  = v;
        d_as2[n*NH + h] = v * asrc[h];
        d_ad2[n*NH + h] = v * adst[h];
    }
}

// ---------------- 9. GAT2 aggregation: warp per dst ----------------
__global__ void k_gat2_agg(const float* bias, float* out) {
    int n = blockIdx.x*4 + (threadIdx.x >> 5);
    int lane = threadIdx.x & 31;
    if (n >= N2) return;
    int beg = d_off2[n], end = d_off2[n+1];
    float total = 0.f;
    #pragma unroll
    for (int h = 0; h < NH; h++) {
        float adst = d_ad2[n*NH + h];
        float m = -1e30f;
        for (int i = beg + lane; i < end; i += 32) {
            int s = d_csr2[i];
            m = fmaxf(m, lrelu(d_as2[s*NH + h] + adst));
        }
        m = warp_max(m);
        float ssum = 0.f, wsum = 0.f;
        for (int i = beg + lane; i < end; i += 32) {
            int s = d_csr2[i];
            float ex = expf(lrelu(d_as2[s*NH + h] + adst) - m);
            ssum += ex;
            wsum += ex * d_h2[s*NH + h];
        }
        ssum = warp_sum(ssum);
        wsum = warp_sum(wsum);
        total += 0.25f * wsum / (ssum + 1e-16f);
    }
    if (lane == 0) out[n] = total + bias[0];
}

// ---------------- launch ----------------
extern "C" void kernel_launch(void* const* d_in, const int* in_sizes, int n_in,
                              void* d_out, int out_size) {
    const int*   cat1   = (const int*)  d_in[0];
    const float* num1   = (const float*)d_in[1];
    const int*   cat2   = (const int*)  d_in[2];
    const float* num2   = (const float*)d_in[3];
    const int*   e1     = (const int*)  d_in[4];
    const int*   e2     = (const int*)  d_in[5];
    const int*   A      = (const int*)  d_in[6];
    const float* emb0   = (const float*)d_in[7];
    const float* emb1   = (const float*)d_in[8];
    const float* emb2   = (const float*)d_in[9];
    const float* g1_lin = (const float*)d_in[10];
    const float* g1_as  = (const float*)d_in[11];
    const float* g1_ad  = (const float*)d_in[12];
    const float* g1_b   = (const float*)d_in[13];
    const float* g2_lin = (const float*)d_in[14];
    const float* g2_as  = (const float*)d_in[15];
    const float* g2_ad  = (const float*)d_in[16];
    const float* g2_b   = (const float*)d_in[17];
    const float* W      = (const float*)d_in[18];
    float* out = (float*)d_out;

    k_pre<<<N1 + N2, 64>>>(cat1, num1, cat2, num2, emb0, emb1, emb2);
    k_M<<<NO, 64>>>(W);
    k_gemm1<<<N1, 256>>>(g1_lin, g1_as, g1_ad);

    // CSR graph 1
    k_initcnt<<<(N1+255)/256, 256>>>(0);
    k_hist<<<(E1N+255)/256, 256>>>(e1, 0);
    k_scan<<<1, 1024>>>(0);
    k_scatter<<<(T1+255)/256, 256>>>(e1, 0);

    // CSR graph 2
    k_initcnt<<<(N2+255)/256, 256>>>(1);
    k_hist<<<(E2N+255)/256, 256>>>(e2, 1);
    k_scan<<<1, 1024>>>(1);
    k_scatter<<<(T2+255)/256, 256>>>(e2, 1);

    k_gat1_agg<<<N1, 128>>>(g1_b);
    k_quad<<<N1, 64>>>();
    k_z2<<<N2, 64>>>();
    k_attn<<<N2, 128>>>(A);
    k_gat2_pre<<<(N2+127)/128, 128>>>(g2_lin, g2_as, g2_ad);
    k_gat2_agg<<<(N2+3)/4, 128>>>(g2_b, out);
}